// round 16
// baseline (speedup 1.0000x reference)
#include <cuda_runtime.h>
#include <cuda_fp16.h>
#include <math.h>

#define BATCH 4
#define CC    256
#define CQ    32
#define NTOK  4096
#define LOG2E 1.4426950408889634f

__device__ __half g_qh[BATCH * NTOK * CQ];
__device__ __half g_ql[BATCH * NTOK * CQ];
__device__ __half g_kh[BATCH * NTOK * CQ];
__device__ __half g_vh[BATCH * CC * NTOK];
__device__ __half g_xh[BATCH * NTOK * CC];
__device__ __half g_xl[BATCH * NTOK * CC];
__device__ __half g_wh[320 * CC];
__device__ __half g_wl[320 * CC];
__device__ float  g_bias[320];

__device__ __forceinline__ void mma16(float4& d, const unsigned* a, unsigned b0, unsigned b1) {
    asm volatile(
        "mma.sync.aligned.m16n8k16.row.col.f32.f16.f16.f32 "
        "{%0,%1,%2,%3},{%4,%5,%6,%7},{%8,%9},{%0,%1,%2,%3};"
        : "+f"(d.x), "+f"(d.y), "+f"(d.z), "+f"(d.w)
        : "r"(a[0]), "r"(a[1]), "r"(a[2]), "r"(a[3]), "r"(b0), "r"(b1));
}
__device__ __forceinline__ void cpa16(unsigned dst, const void* src) {
    asm volatile("cp.async.ca.shared.global [%0], [%1], 16;" :: "r"(dst), "l"(src));
}
__device__ __forceinline__ float ex2(float x) {
    float r; asm("ex2.approx.f32 %0, %1;" : "=f"(r) : "f"(x)); return r;
}

// ============ Kernel A: weight convert ============
__global__ __launch_bounds__(256) void convw_kernel(
    const float* __restrict__ wq, const float* __restrict__ bq,
    const float* __restrict__ wk, const float* __restrict__ bk,
    const float* __restrict__ wv, const float* __restrict__ bv)
{
    int row = blockIdx.x, t = threadIdx.x;
    float scale = (row < CQ) ? LOG2E : 1.0f;
    const float* src;
    if (row < CQ)          src = wq + (size_t)row * CC;
    else if (row < 2 * CQ) src = wk + (size_t)(row - CQ) * CC;
    else                   src = wv + (size_t)(row - 2 * CQ) * CC;
    float v = src[t] * scale;
    __half h = __float2half_rn(v);
    g_wh[row * CC + t] = h;
    g_wl[row * CC + t] = __float2half_rn(v - __half2float(h));
    if (t == 0) {
        float bb = (row < CQ) ? bq[row] : (row < 2 * CQ) ? bk[row - CQ] : bv[row - 2 * CQ];
        g_bias[row] = bb * scale;
    }
}

// ============ Kernel B: x transpose + hi/lo split ============
__global__ __launch_bounds__(256) void convx_kernel(const float* __restrict__ x)
{
    __shared__ float sm[64 * 65];
    const int n0 = blockIdx.x * 64, c0 = blockIdx.y * 64, b = blockIdx.z;
    const int t = threadIdx.x;
#pragma unroll
    for (int p = 0; p < 4; p++) {
        int idx = p * 256 + t, c = idx >> 4, l = idx & 15;
        float4 v = *(const float4*)(x + ((size_t)b * CC + c0 + c) * NTOK + n0 + 4 * l);
        sm[c * 65 + 4 * l + 0] = v.x; sm[c * 65 + 4 * l + 1] = v.y;
        sm[c * 65 + 4 * l + 2] = v.z; sm[c * 65 + 4 * l + 3] = v.w;
    }
    __syncthreads();
#pragma unroll
    for (int p = 0; p < 2; p++) {
        int idx = p * 256 + t, n = idx >> 3, cc = idx & 7;
        __align__(16) __half hs[8], ls[8];
#pragma unroll
        for (int i = 0; i < 8; i++) {
            float v = sm[(8 * cc + i) * 65 + n];
            __half h = __float2half_rn(v);
            hs[i] = h;
            ls[i] = __float2half_rn(v - __half2float(h));
        }
        size_t off = ((size_t)b * NTOK + n0 + n) * CC + c0 + 8 * cc;
        *(uint4*)(g_xh + off) = *(uint4*)hs;
        *(uint4*)(g_xl + off) = *(uint4*)ls;
    }
}

// ============ Kernel C: projections on tensor cores ============
#define PXH 0
#define PXL 8448
#define PWH 16896
#define PWL 25344
#define PROJ_WORDS 33792

__global__ __launch_bounds__(256, 1) void projmma_kernel()
{
    extern __shared__ unsigned su[];
    const int t = threadIdx.x, w = t >> 5, lane = t & 31;
    const int quad = lane & 3, qr = lane >> 2;
    const int n0 = blockIdx.x * 64, rg = blockIdx.y, b = blockIdx.z;
    const int r0 = rg * 64;
    const int mr = 16 * (w >> 1), th = 32 * (w & 1);
    const unsigned sbase = (unsigned)__cvta_generic_to_shared(su);

#pragma unroll
    for (int p = 0; p < 8; p++) {
        int idx = p * 256 + t, row = idx >> 5, ch = idx & 31;
        size_t xoff = ((size_t)b * NTOK + n0 + row) * CC + ch * 8;
        size_t woff = (size_t)(r0 + row) * CC + ch * 8;
        cpa16(sbase + (PXH + row * 132 + ch * 4) * 4, g_xh + xoff);
        cpa16(sbase + (PXL + row * 132 + ch * 4) * 4, g_xl + xoff);
        cpa16(sbase + (PWH + row * 132 + ch * 4) * 4, g_wh + woff);
        cpa16(sbase + (PWL + row * 132 + ch * 4) * 4, g_wl + woff);
    }
    asm volatile("cp.async.commit_group;" ::: "memory");
    asm volatile("cp.async.wait_group 0;" ::: "memory");
    __syncthreads();

    const unsigned* XH = su + PXH;
    const unsigned* XL = su + PXL;
    const unsigned* WH = su + PWH;
    const unsigned* WL = su + PWL;

    float4 acc[4];
#pragma unroll
    for (int nt = 0; nt < 4; nt++) acc[nt] = make_float4(0.f, 0.f, 0.f, 0.f);

#pragma unroll
    for (int ks = 0; ks < 16; ks++) {
        unsigned ah[4], al[4];
        int ba = (mr + qr) * 132 + ks * 8 + quad;
        ah[0] = WH[ba];        ah[1] = WH[ba + 8 * 132];
        ah[2] = WH[ba + 4];    ah[3] = WH[ba + 8 * 132 + 4];
        al[0] = WL[ba];        al[1] = WL[ba + 8 * 132];
        al[2] = WL[ba + 4];    al[3] = WL[ba + 8 * 132 + 4];
#pragma unroll
        for (int nt = 0; nt < 4; nt++) {
            int bb = (th + 8 * nt + qr) * 132 + ks * 8 + quad;
            unsigned bh0 = XH[bb], bh1 = XH[bb + 4];
            unsigned bl0 = XL[bb], bl1 = XL[bb + 4];
            mma16(acc[nt], ah, bh0, bh1);
            mma16(acc[nt], al, bh0, bh1);
            mma16(acc[nt], ah, bl0, bl1);
        }
    }
    __syncthreads();

    float* sT = (float*)(su + PXH);   // [64 rows][68]
#pragma unroll
    for (int nt = 0; nt < 4; nt++) {
        int r1 = mr + qr, c = th + 8 * nt + 2 * quad;
        sT[r1 * 68 + c]           = acc[nt].x;
        sT[r1 * 68 + c + 1]       = acc[nt].y;
        sT[(r1 + 8) * 68 + c]     = acc[nt].z;
        sT[(r1 + 8) * 68 + c + 1] = acc[nt].w;
    }
    __syncthreads();

    if (rg == 0) {
        int n = t & 63, rh = t >> 6;
        __align__(16) __half hs[16], ls[16];
#pragma unroll
        for (int i = 0; i < 16; i++) {
            float v = sT[(16 * rh + i) * 68 + n] + g_bias[16 * rh + i];
            __half h = __float2half_rn(v);
            hs[i] = h;
            ls[i] = __float2half_rn(v - __half2float(h));
        }
        size_t tok = (size_t)b * NTOK + n0 + n;
        if (rh < 2) {
            __half* dh = g_qh + tok * CQ + 16 * rh;
            __half* dl = g_ql + tok * CQ + 16 * rh;
            *(uint4*)dh = *(uint4*)hs; *(uint4*)(dh + 8) = ((uint4*)hs)[1];
            *(uint4*)dl = *(uint4*)ls; *(uint4*)(dl + 8) = ((uint4*)ls)[1];
        } else {
            __half* dk = g_kh + tok * CQ + 16 * (rh - 2);
            *(uint4*)dk = *(uint4*)hs; *(uint4*)(dk + 8) = ((uint4*)hs)[1];
        }
    } else {
        int r = t & 63, tc = t >> 6;
        int o = r0 - 64 + r;
        float bias = g_bias[r0 + r];
        __align__(16) __half hs[16];
#pragma unroll
        for (int i = 0; i < 16; i++)
            hs[i] = __float2half_rn(sT[r * 68 + 16 * tc + i] + bias);
        __half* dst = g_vh + ((size_t)b * CC + o) * NTOK + n0 + 16 * tc;
        *(uint4*)dst = *(uint4*)hs; *(uint4*)(dst + 8) = ((uint4*)hs)[1];
    }
}

// ============ Kernel 2: warp-specialized flash attention ============
// words: Qh 0-1280, Ql 1280-2560, K0 2560-3840, K1 3840-5120,
//        V0 5120-14336, V1 14336-23552, P0 23552-25856, P1 25856-28160,
//        AL0 28160, AL1 28224, SC 28288
#define OQH  0
#define OQL  1280
#define OK0  2560
#define OK1  3840
#define OV0  5120
#define OV1  14336
#define OP0  23552
#define OP1  25856
#define OAL0 28160
#define OAL1 28224
#define OSC  28288
#define SMEM_WORDS 28352

__global__ __launch_bounds__(384, 1) void attn_kernel(
    const float* __restrict__ x,
    const float* __restrict__ gamma,
    float* __restrict__ out)
{
    extern __shared__ unsigned su[];
    float* sSc = (float*)(su + OSC);

    const int t = threadIdx.x, w = t >> 5, lane = t & 31;
    const int quad = lane & 3, qr = lane >> 2;
    const int b = blockIdx.x >> 6, q0 = (blockIdx.x & 63) * 64;
    const unsigned sbase = (unsigned)__cvta_generic_to_shared(su);

    const __half* khp = g_kh + (size_t)b * NTOK * CQ;
    const __half* vb  = g_vh + (size_t)b * CC * NTOK;

    // ---- Q staging (hi + lo) ----
    for (int idx = t; idx < 512; idx += 384) {
        int arr = idx >> 8, row = (idx >> 2) & 63, ch = idx & 3;
        size_t off = ((size_t)b * NTOK + q0 + row) * CQ + ch * 8;
        const __half* src = arr ? g_ql : g_qh;
        unsigned dst = arr ? OQL : OQH;
        *(uint4*)((float*)su + dst + row * 20 + ch * 4) = *(const uint4*)(src + off);
    }

    // ---- prologue loads: K(0) alone, then {V(0), K(1)} ----
#pragma unroll
    for (int p = 0; p < 6; p++) {
        int idx = t + 384 * p;
        if (idx >= 2048) {
            int ki = idx - 2048, krr = ki >> 2, kcc = ki & 3;
            cpa16(sbase + (OK0 + krr * 20 + kcc * 4) * 4, khp + (size_t)krr * CQ + kcc * 8);
        }
    }
    asm volatile("cp.async.commit_group;" ::: "memory");
#pragma unroll
    for (int p = 0; p < 6; p++) {
        int idx = t + 384 * p;
        if (idx < 2048) {
            int o = idx >> 3, ch = idx & 7;
            cpa16(sbase + (OV0 + o * 36 + ch * 4) * 4, vb + (size_t)o * NTOK + ch * 8);
        } else {
            int ki = idx - 2048, krr = ki >> 2, kcc = ki & 3;
            cpa16(sbase + (OK1 + krr * 20 + kcc * 4) * 4,
                  khp + (size_t)(64 + krr) * CQ + kcc * 8);
        }
    }
    asm volatile("cp.async.commit_group;" ::: "memory");
    asm volatile("cp.async.wait_group 1;" ::: "memory");
    __syncthreads();   // Q + K(0) visible

    // ---- per-role state ----
    float4 acc[4][4];
    unsigned ah[2][4], alq[2][4];
    float run_m0 = -1e4f, run_m1 = -1e4f, run_l0 = 0.f, run_l1 = 0.f;
    const int o_base = 32 * w;          // PV warps (w<8)
    const int r0s = 16 * (w - 8);       // softmax warps (w>=8)

    if (w < 8) {
#pragma unroll
        for (int ms = 0; ms < 4; ms++)
#pragma unroll
            for (int ot = 0; ot < 4; ot++) acc[ms][ot] = make_float4(0.f, 0.f, 0.f, 0.f);
    } else {
        const unsigned* uQh = su + OQH;
        const unsigned* uQl = su + OQL;
#pragma unroll
        for (int ks = 0; ks < 2; ks++) {
            int base = (r0s + qr) * 20 + ks * 8 + quad;
            ah[ks][0] = uQh[base];      ah[ks][1] = uQh[base + 160];
            ah[ks][2] = uQh[base + 4];  ah[ks][3] = uQh[base + 164];
            alq[ks][0] = uQl[base];     alq[ks][1] = uQl[base + 160];
            alq[ks][2] = uQl[base + 4]; alq[ks][3] = uQl[base + 164];
        }
    }

    // softmax of a 64-key tile held in K buffer kb_off; writes P/alpha parity pb
    auto softmax_tile = [&](const unsigned* uKh, unsigned* uPd, float* sAld) {
        float4 sreg[8];
#pragma unroll
        for (int nt = 0; nt < 8; nt++) {
            float4 c = make_float4(0.f, 0.f, 0.f, 0.f);
#pragma unroll
            for (int ks = 0; ks < 2; ks++) {
                int kb = (nt * 8 + qr) * 20 + ks * 8 + quad;
                unsigned bh0 = uKh[kb], bh1 = uKh[kb + 4];
                mma16(c, ah[ks], bh0, bh1);
                mma16(c, alq[ks], bh0, bh1);
            }
            sreg[nt] = c;
        }
        float mA = -1e30f, mB = -1e30f;
#pragma unroll
        for (int nt = 0; nt < 8; nt++) {
            mA = fmaxf(mA, fmaxf(sreg[nt].x, sreg[nt].y));
            mB = fmaxf(mB, fmaxf(sreg[nt].z, sreg[nt].w));
        }
        mA = fmaxf(mA, __shfl_xor_sync(0xffffffffu, mA, 1));
        mA = fmaxf(mA, __shfl_xor_sync(0xffffffffu, mA, 2));
        mB = fmaxf(mB, __shfl_xor_sync(0xffffffffu, mB, 1));
        mB = fmaxf(mB, __shfl_xor_sync(0xffffffffu, mB, 2));
        float mAn = fmaxf(run_m0, mA), mBn = fmaxf(run_m1, mB);
        float alA = ex2(run_m0 - mAn), alB = ex2(run_m1 - mBn);
        run_m0 = mAn; run_m1 = mBn;
        float sA = 0.f, sB = 0.f;
        int rw = r0s + qr;
#pragma unroll
        for (int nt = 0; nt < 8; nt++) {
            float px = ex2(sreg[nt].x - mAn), py = ex2(sreg[nt].y - mAn);
            float pz = ex2(sreg[nt].z - mBn), pw = ex2(sreg[nt].w - mBn);
            sA += px + py; sB += pz + pw;
            __half2 hA = __floats2half2_rn(px, py);
            __half2 hB = __floats2half2_rn(pz, pw);
            uPd[rw * 36 + nt * 4 + quad]       = *(unsigned*)&hA;
            uPd[(rw + 8) * 36 + nt * 4 + quad] = *(unsigned*)&hB;
        }
        sA += __shfl_xor_sync(0xffffffffu, sA, 1);
        sA += __shfl_xor_sync(0xffffffffu, sA, 2);
        sB += __shfl_xor_sync(0xffffffffu, sB, 1);
        sB += __shfl_xor_sync(0xffffffffu, sB, 2);
        run_l0 = run_l0 * alA + sA;
        run_l1 = run_l1 * alB + sB;
        if (quad == 0) { sAld[rw] = alA; sAld[rw + 8] = alB; }
    };

    // bootstrap: P(0), alpha(0)
    if (w >= 8) softmax_tile(su + OK0, su + OP0, (float*)(su + OAL0));

    for (int kt = 0; kt < 64; kt++) {
        asm volatile("cp.async.wait_group 0;" ::: "memory");
        __syncthreads();   // P(kt), alpha(kt), V(kt), K(kt+1) visible

        // issue {V(kt+1), K(kt+2)}
        if (kt + 1 < 64) {
            int jV = (kt + 1) * 64, jK = (kt + 2) * 64;
            unsigned vbuf = ((kt + 1) & 1) ? OV1 : OV0;
            unsigned kbuf = (kt & 1) ? OK1 : OK0;   // K(kt+2) parity == kt
            bool doK = (kt + 2 < 64);
#pragma unroll
            for (int p = 0; p < 6; p++) {
                int idx = t + 384 * p;
                if (idx < 2048) {
                    int o = idx >> 3, ch = idx & 7;
                    cpa16(sbase + (vbuf + o * 36 + ch * 4) * 4,
                          vb + (size_t)o * NTOK + jV + ch * 8);
                } else if (doK) {
                    int ki = idx - 2048, krr = ki >> 2, kcc = ki & 3;
                    cpa16(sbase + (kbuf + krr * 20 + kcc * 4) * 4,
                          khp + (size_t)(jK + krr) * CQ + kcc * 8);
                }
            }
        }
        asm volatile("cp.async.commit_group;" ::: "memory");

        if (w < 8) {
            // ---- PV(kt): rescale + 64 mma ----
            const unsigned* uP = su + ((kt & 1) ? OP1 : OP0);
            const unsigned* uV = su + ((kt & 1) ? OV1 : OV0);
            const float* sAl = (const float*)(su + ((kt & 1) ? OAL1 : OAL0));
            float aA[4], aB[4];
#pragma unroll
            for (int ms = 0; ms < 4; ms++) {
                aA[ms] = sAl[16 * ms + qr];
                aB[ms] = sAl[16 * ms + qr + 8];
            }
#pragma unroll
            for (int ms = 0; ms < 4; ms++)
#pragma unroll
                for (int ot = 0; ot < 4; ot++) {
                    acc[ms][ot].x *= aA[ms]; acc[ms][ot].y *= aA[ms];
                    acc[ms][ot].z *= aB[ms]; acc[ms][ot].w *= aB[ms];
                }
#pragma unroll
            for (int ks = 0; ks < 4; ks++) {
                unsigned pf[4][4];
#pragma unroll
                for (int ms = 0; ms < 4; ms++) {
                    int ai = (16 * ms + qr) * 36 + ks * 8 + quad;
                    pf[ms][0] = uP[ai];     pf[ms][1] = uP[ai + 8 * 36];
                    pf[ms][2] = uP[ai + 4]; pf[ms][3] = uP[ai + 8 * 36 + 4];
                }
#pragma unroll
                for (int ot = 0; ot < 4; ot++) {
                    int vi = (o_base + 8 * ot + qr) * 36 + ks * 8 + quad;
                    unsigned v0 = uV[vi], v1 = uV[vi + 4];
#pragma unroll
                    for (int ms = 0; ms < 4; ms++)
                        mma16(acc[ms][ot], pf[ms], v0, v1);
                }
            }
        } else if (kt + 1 < 64) {
            // ---- S(kt+1) + softmax -> P(kt+1) ----
            softmax_tile(su + (((kt + 1) & 1) ? OK1 : OK0),
                         su + (((kt + 1) & 1) ? OP1 : OP0),
                         (float*)(su + (((kt + 1) & 1) ? OAL1 : OAL0)));
        }
    }

    // ---- epilogue ----
    if (w >= 8 && quad == 0) {
        float gm = gamma[0];
        sSc[r0s + qr]     = gm / run_l0;
        sSc[r0s + qr + 8] = gm / run_l1;
    }
    __syncthreads();

    if (w < 8) {
        const float* xb = x   + (size_t)b * CC * NTOK;
        float*       ob = out + (size_t)b * CC * NTOK;
#pragma unroll
        for (int ms = 0; ms < 4; ms++) {
            float scA = sSc[16 * ms + qr];
            float scB = sSc[16 * ms + qr + 8];
            int m = q0 + 16 * ms + qr;
#pragma unroll
            for (int ot = 0; ot < 4; ot++) {
                int o = o_base + 8 * ot + 2 * quad;
                float4 c = acc[ms][ot];
                size_t i00 = (size_t)o * NTOK + m;
                size_t i10 = (size_t)(o + 1) * NTOK + m;
                ob[i00]     = fmaf(scA, c.x, xb[i00]);
                ob[i10]     = fmaf(scA, c.y, xb[i10]);
                ob[i00 + 8] = fmaf(scB, c.z, xb[i00 + 8]);
                ob[i10 + 8] = fmaf(scB, c.w, xb[i10 + 8]);
            }
        }
    }
}

// ============ launch ============
extern "C" void kernel_launch(void* const* d_in, const int* in_sizes, int n_in,
                              void* d_out, int out_size)
{
    const float* x     = (const float*)d_in[0];
    const float* wq    = (const float*)d_in[1];
    const float* bq    = (const float*)d_in[2];
    const float* wk    = (const float*)d_in[3];
    const float* bk    = (const float*)d_in[4];
    const float* wv    = (const float*)d_in[5];
    const float* bv    = (const float*)d_in[6];
    const float* gamma = (const float*)d_in[7];
    float* out = (float*)d_out;

    convw_kernel<<<320, 256>>>(wq, bq, wk, bk, wv, bv);
    convx_kernel<<<dim3(NTOK / 64, CC / 64, BATCH), 256>>>(x);

    const int proj_bytes = PROJ_WORDS * 4;
    cudaFuncSetAttribute(projmma_kernel, cudaFuncAttributeMaxDynamicSharedMemorySize, proj_bytes);
    projmma_kernel<<<dim3(NTOK / 64, 5, BATCH), 256, proj_bytes>>>();

    const int smem_bytes = SMEM_WORDS * 4;   // 113408
    cudaFuncSetAttribute(attn_kernel, cudaFuncAttributeMaxDynamicSharedMemorySize, smem_bytes);
    attn_kernel<<<BATCH * (NTOK / 64), 384, smem_bytes>>>(x, gamma, out);
}

// round 17
// speedup vs baseline: 1.1391x; 1.1391x over previous
#include <cuda_runtime.h>
#include <cuda_fp16.h>
#include <math.h>

#define BATCH 4
#define CC    256
#define CQ    32
#define NTOK  4096
#define LOG2E 1.4426950408889634f

__device__ __half g_qh[BATCH * NTOK * CQ];
__device__ __half g_ql[BATCH * NTOK * CQ];
__device__ __half g_kh[BATCH * NTOK * CQ];
__device__ __half g_vh[BATCH * CC * NTOK];
__device__ __half g_xh[BATCH * NTOK * CC];
__device__ __half g_xl[BATCH * NTOK * CC];
__device__ __half g_wh[320 * CC];
__device__ __half g_wl[320 * CC];
__device__ float  g_bias[320];

__device__ __forceinline__ void mma16(float4& d, const unsigned* a, unsigned b0, unsigned b1) {
    asm volatile(
        "mma.sync.aligned.m16n8k16.row.col.f32.f16.f16.f32 "
        "{%0,%1,%2,%3},{%4,%5,%6,%7},{%8,%9},{%0,%1,%2,%3};"
        : "+f"(d.x), "+f"(d.y), "+f"(d.z), "+f"(d.w)
        : "r"(a[0]), "r"(a[1]), "r"(a[2]), "r"(a[3]), "r"(b0), "r"(b1));
}
__device__ __forceinline__ void cpa16(unsigned dst, const void* src) {
    asm volatile("cp.async.ca.shared.global [%0], [%1], 16;" :: "r"(dst), "l"(src));
}
__device__ __forceinline__ float ex2(float x) {
    float r; asm("ex2.approx.f32 %0, %1;" : "=f"(r) : "f"(x)); return r;
}
__device__ __forceinline__ void ldm4(unsigned& d0, unsigned& d1, unsigned& d2, unsigned& d3,
                                     unsigned addr) {
    asm volatile("ldmatrix.sync.aligned.m8n8.x4.shared.b16 {%0,%1,%2,%3}, [%4];"
        : "=r"(d0), "=r"(d1), "=r"(d2), "=r"(d3) : "r"(addr));
}

// ============ Kernel A: weight convert ============
__global__ __launch_bounds__(256) void convw_kernel(
    const float* __restrict__ wq, const float* __restrict__ bq,
    const float* __restrict__ wk, const float* __restrict__ bk,
    const float* __restrict__ wv, const float* __restrict__ bv)
{
    int row = blockIdx.x, t = threadIdx.x;
    float scale = (row < CQ) ? LOG2E : 1.0f;
    const float* src;
    if (row < CQ)          src = wq + (size_t)row * CC;
    else if (row < 2 * CQ) src = wk + (size_t)(row - CQ) * CC;
    else                   src = wv + (size_t)(row - 2 * CQ) * CC;
    float v = src[t] * scale;
    __half h = __float2half_rn(v);
    g_wh[row * CC + t] = h;
    g_wl[row * CC + t] = __float2half_rn(v - __half2float(h));
    if (t == 0) {
        float bb = (row < CQ) ? bq[row] : (row < 2 * CQ) ? bk[row - CQ] : bv[row - 2 * CQ];
        g_bias[row] = bb * scale;
    }
}

// ============ Kernel B: x transpose + hi/lo split ============
__global__ __launch_bounds__(256) void convx_kernel(const float* __restrict__ x)
{
    __shared__ float sm[64 * 65];
    const int n0 = blockIdx.x * 64, c0 = blockIdx.y * 64, b = blockIdx.z;
    const int t = threadIdx.x;
#pragma unroll
    for (int p = 0; p < 4; p++) {
        int idx = p * 256 + t, c = idx >> 4, l = idx & 15;
        float4 v = *(const float4*)(x + ((size_t)b * CC + c0 + c) * NTOK + n0 + 4 * l);
        sm[c * 65 + 4 * l + 0] = v.x; sm[c * 65 + 4 * l + 1] = v.y;
        sm[c * 65 + 4 * l + 2] = v.z; sm[c * 65 + 4 * l + 3] = v.w;
    }
    __syncthreads();
#pragma unroll
    for (int p = 0; p < 2; p++) {
        int idx = p * 256 + t, n = idx >> 3, cc = idx & 7;
        __align__(16) __half hs[8], ls[8];
#pragma unroll
        for (int i = 0; i < 8; i++) {
            float v = sm[(8 * cc + i) * 65 + n];
            __half h = __float2half_rn(v);
            hs[i] = h;
            ls[i] = __float2half_rn(v - __half2float(h));
        }
        size_t off = ((size_t)b * NTOK + n0 + n) * CC + c0 + 8 * cc;
        *(uint4*)(g_xh + off) = *(uint4*)hs;
        *(uint4*)(g_xl + off) = *(uint4*)ls;
    }
}

// ============ Kernel C: projections on tensor cores ============
#define PXH 0
#define PXL 8448
#define PWH 16896
#define PWL 25344
#define PROJ_WORDS 33792

__global__ __launch_bounds__(256, 1) void projmma_kernel()
{
    extern __shared__ unsigned su[];
    const int t = threadIdx.x, w = t >> 5, lane = t & 31;
    const int quad = lane & 3, qr = lane >> 2;
    const int n0 = blockIdx.x * 64, rg = blockIdx.y, b = blockIdx.z;
    const int r0 = rg * 64;
    const int mr = 16 * (w >> 1), th = 32 * (w & 1);
    const unsigned sbase = (unsigned)__cvta_generic_to_shared(su);

#pragma unroll
    for (int p = 0; p < 8; p++) {
        int idx = p * 256 + t, row = idx >> 5, ch = idx & 31;
        size_t xoff = ((size_t)b * NTOK + n0 + row) * CC + ch * 8;
        size_t woff = (size_t)(r0 + row) * CC + ch * 8;
        cpa16(sbase + (PXH + row * 132 + ch * 4) * 4, g_xh + xoff);
        cpa16(sbase + (PXL + row * 132 + ch * 4) * 4, g_xl + xoff);
        cpa16(sbase + (PWH + row * 132 + ch * 4) * 4, g_wh + woff);
        cpa16(sbase + (PWL + row * 132 + ch * 4) * 4, g_wl + woff);
    }
    asm volatile("cp.async.commit_group;" ::: "memory");
    asm volatile("cp.async.wait_group 0;" ::: "memory");
    __syncthreads();

    const unsigned* XH = su + PXH;
    const unsigned* XL = su + PXL;
    const unsigned* WH = su + PWH;
    const unsigned* WL = su + PWL;

    float4 acc[4];
#pragma unroll
    for (int nt = 0; nt < 4; nt++) acc[nt] = make_float4(0.f, 0.f, 0.f, 0.f);

#pragma unroll
    for (int ks = 0; ks < 16; ks++) {
        unsigned ah[4], al[4];
        int ba = (mr + qr) * 132 + ks * 8 + quad;
        ah[0] = WH[ba];        ah[1] = WH[ba + 8 * 132];
        ah[2] = WH[ba + 4];    ah[3] = WH[ba + 8 * 132 + 4];
        al[0] = WL[ba];        al[1] = WL[ba + 8 * 132];
        al[2] = WL[ba + 4];    al[3] = WL[ba + 8 * 132 + 4];
#pragma unroll
        for (int nt = 0; nt < 4; nt++) {
            int bb = (th + 8 * nt + qr) * 132 + ks * 8 + quad;
            unsigned bh0 = XH[bb], bh1 = XH[bb + 4];
            unsigned bl0 = XL[bb], bl1 = XL[bb + 4];
            mma16(acc[nt], ah, bh0, bh1);
            mma16(acc[nt], al, bh0, bh1);
            mma16(acc[nt], ah, bl0, bl1);
        }
    }
    __syncthreads();

    float* sT = (float*)(su + PXH);   // [64 rows][68]
#pragma unroll
    for (int nt = 0; nt < 4; nt++) {
        int r1 = mr + qr, c = th + 8 * nt + 2 * quad;
        sT[r1 * 68 + c]           = acc[nt].x;
        sT[r1 * 68 + c + 1]       = acc[nt].y;
        sT[(r1 + 8) * 68 + c]     = acc[nt].z;
        sT[(r1 + 8) * 68 + c + 1] = acc[nt].w;
    }
    __syncthreads();

    if (rg == 0) {
        int n = t & 63, rh = t >> 6;
        __align__(16) __half hs[16], ls[16];
#pragma unroll
        for (int i = 0; i < 16; i++) {
            float v = sT[(16 * rh + i) * 68 + n] + g_bias[16 * rh + i];
            __half h = __float2half_rn(v);
            hs[i] = h;
            ls[i] = __float2half_rn(v - __half2float(h));
        }
        size_t tok = (size_t)b * NTOK + n0 + n;
        if (rh < 2) {
            __half* dh = g_qh + tok * CQ + 16 * rh;
            __half* dl = g_ql + tok * CQ + 16 * rh;
            *(uint4*)dh = *(uint4*)hs; *(uint4*)(dh + 8) = ((uint4*)hs)[1];
            *(uint4*)dl = *(uint4*)ls; *(uint4*)(dl + 8) = ((uint4*)ls)[1];
        } else {
            __half* dk = g_kh + tok * CQ + 16 * (rh - 2);
            *(uint4*)dk = *(uint4*)hs; *(uint4*)(dk + 8) = ((uint4*)hs)[1];
        }
    } else {
        int r = t & 63, tc = t >> 6;
        int o = r0 - 64 + r;
        float bias = g_bias[r0 + r];
        __align__(16) __half hs[16];
#pragma unroll
        for (int i = 0; i < 16; i++)
            hs[i] = __float2half_rn(sT[r * 68 + 16 * tc + i] + bias);
        __half* dst = g_vh + ((size_t)b * CC + o) * NTOK + n0 + 16 * tc;
        *(uint4*)dst = *(uint4*)hs; *(uint4*)(dst + 8) = ((uint4*)hs)[1];
    }
}

// ============ Kernel 2: flash attention, 64-key tiles + ldmatrix ============
#define OQH  0
#define OQL  1280
#define OP   0
#define OKH0 2560
#define OKH1 3840
#define OV0  5120
#define OV1  14336
#define OAL  23552
#define OSC  23616
#define SMEM_WORDS 23680

__global__ __launch_bounds__(256, 2) void attn_kernel(
    const float* __restrict__ x,
    const float* __restrict__ gamma,
    float* __restrict__ out)
{
    extern __shared__ unsigned su[];
    unsigned* uP = su + OP;
    float* sAl = (float*)(su + OAL);
    float* sSc = (float*)(su + OSC);

    const int t = threadIdx.x, w = t >> 5, lane = t & 31;
    const int quad = lane & 3, qr = lane >> 2;
    const int m_base = 32 * (w >> 2), o_base = 64 * (w & 3);
    const int b = blockIdx.x >> 6, q0 = (blockIdx.x & 63) * 64;
    const unsigned sbase = (unsigned)__cvta_generic_to_shared(su);

    // ldmatrix per-lane row/col splits
    const int arow = (lane & 7) + 8 * ((lane >> 3) & 1);   // A-type (P)
    const int acol = 4 * (lane >> 4);
    const int brow = 8 * (lane >> 4) + (lane & 7);         // B-type (K, V)
    const int bcol = 4 * ((lane >> 3) & 1);

    const __half* khp = g_kh + (size_t)b * NTOK * CQ;
    const __half* vb  = g_vh + (size_t)b * CC * NTOK;

    {
        int r = t >> 2, qw = t & 3;
        size_t off = ((size_t)b * NTOK + q0 + r) * CQ + qw * 8;
        *(uint4*)(su + OQH + r * 20 + qw * 4) = *(const uint4*)(g_qh + off);
        *(uint4*)(su + OQL + r * 20 + qw * 4) = *(const uint4*)(g_ql + off);
    }

    const int kr = t >> 2, kc = t & 3;
    const __half* ksrc = khp + (size_t)kr * CQ + kc * 8;
    const unsigned koff = kr * 20 + kc * 4;
    const int vrow = t >> 3, vci = t & 7;
    const __half* vsrc = vb + (size_t)vrow * NTOK + vci * 8;
    const unsigned voff = vrow * 36 + vci * 4;

#pragma unroll
    for (int r = 0; r < 8; r++)
        cpa16(sbase + (OV0 + voff + (32 * r) * 36) * 4, vsrc + (size_t)(32 * r) * NTOK);
    cpa16(sbase + (OKH0 + koff) * 4, ksrc);
    asm volatile("cp.async.commit_group;" ::: "memory");
    asm volatile("cp.async.wait_group 0;" ::: "memory");
    __syncthreads();

    unsigned ah[2][4], alq[2][4];
    if (w < 4) {
        const unsigned* uQh = su + OQH;
        const unsigned* uQl = su + OQL;
#pragma unroll
        for (int ks = 0; ks < 2; ks++) {
            int base = (16 * w + qr) * 20 + ks * 8 + quad;
            ah[ks][0] = uQh[base];      ah[ks][1] = uQh[base + 160];
            ah[ks][2] = uQh[base + 4];  ah[ks][3] = uQh[base + 164];
            alq[ks][0] = uQl[base];     alq[ks][1] = uQl[base + 160];
            alq[ks][2] = uQl[base + 4]; alq[ks][3] = uQl[base + 164];
        }
    }

    float4 acc[2][8];
#pragma unroll
    for (int s = 0; s < 2; s++)
#pragma unroll
        for (int o = 0; o < 8; o++) acc[s][o] = make_float4(0.f, 0.f, 0.f, 0.f);
    float run_m0 = -1e4f, run_m1 = -1e4f, run_l0 = 0.f, run_l1 = 0.f;

    for (int kt = 0; kt < 64; kt++) {
        const int cur = kt & 1;
        const unsigned kbw = cur ? OKH1 : OKH0;
        const unsigned vbw = cur ? OV1 : OV0;

        if (kt + 1 < 64) {
            int jn = (kt + 1) * 64;
            unsigned vo = cur ? OV0 : OV1;
            unsigned ko = cur ? OKH0 : OKH1;
#pragma unroll
            for (int r = 0; r < 8; r++)
                cpa16(sbase + (vo + voff + (32 * r) * 36) * 4,
                      vsrc + jn + (size_t)(32 * r) * NTOK);
            cpa16(sbase + (ko + koff) * 4, ksrc + (size_t)jn * CQ);
            asm volatile("cp.async.commit_group;" ::: "memory");
        }

        if (w < 4) {   // S (16 rows x 64 cols) + online softmax
            float4 sreg[8];
#pragma unroll
            for (int nt = 0; nt < 8; nt++) sreg[nt] = make_float4(0.f, 0.f, 0.f, 0.f);
#pragma unroll
            for (int ks = 0; ks < 2; ks++) {
#pragma unroll
                for (int ntp = 0; ntp < 4; ntp++) {
                    unsigned b0a, b1a, b0b, b1b;
                    ldm4(b0a, b1a, b0b, b1b,
                         sbase + (kbw + (16 * ntp + brow) * 20 + ks * 8 + bcol) * 4);
                    mma16(sreg[2 * ntp],     ah[ks],  b0a, b1a);
                    mma16(sreg[2 * ntp],     alq[ks], b0a, b1a);
                    mma16(sreg[2 * ntp + 1], ah[ks],  b0b, b1b);
                    mma16(sreg[2 * ntp + 1], alq[ks], b0b, b1b);
                }
            }
            float mA = -1e30f, mB = -1e30f;
#pragma unroll
            for (int nt = 0; nt < 8; nt++) {
                mA = fmaxf(mA, fmaxf(sreg[nt].x, sreg[nt].y));
                mB = fmaxf(mB, fmaxf(sreg[nt].z, sreg[nt].w));
            }
            mA = fmaxf(mA, __shfl_xor_sync(0xffffffffu, mA, 1));
            mA = fmaxf(mA, __shfl_xor_sync(0xffffffffu, mA, 2));
            mB = fmaxf(mB, __shfl_xor_sync(0xffffffffu, mB, 1));
            mB = fmaxf(mB, __shfl_xor_sync(0xffffffffu, mB, 2));
            float mAn = fmaxf(run_m0, mA), mBn = fmaxf(run_m1, mB);
            float alA = ex2(run_m0 - mAn), alB = ex2(run_m1 - mBn);
            run_m0 = mAn; run_m1 = mBn;
            float sA = 0.f, sB = 0.f;
            int rw = 16 * w + qr;
#pragma unroll
            for (int nt = 0; nt < 8; nt++) {
                float px = ex2(sreg[nt].x - mAn), py = ex2(sreg[nt].y - mAn);
                float pz = ex2(sreg[nt].z - mBn), pw = ex2(sreg[nt].w - mBn);
                sA += px + py; sB += pz + pw;
                __half2 hA = __floats2half2_rn(px, py);
                __half2 hB = __floats2half2_rn(pz, pw);
                uP[rw * 36 + nt * 4 + quad]       = *(unsigned*)&hA;
                uP[(rw + 8) * 36 + nt * 4 + quad] = *(unsigned*)&hB;
            }
            sA += __shfl_xor_sync(0xffffffffu, sA, 1);
            sA += __shfl_xor_sync(0xffffffffu, sA, 2);
            sB += __shfl_xor_sync(0xffffffffu, sB, 1);
            sB += __shfl_xor_sync(0xffffffffu, sB, 2);
            run_l0 = run_l0 * alA + sA;
            run_l1 = run_l1 * alB + sB;
            if (quad == 0) { sAl[rw] = alA; sAl[rw + 8] = alB; }
        }
        __syncthreads();   // P + alphas ready

        // rescale + PV (ldmatrix fragments)
        float aA0 = sAl[m_base + qr],      aB0 = sAl[m_base + qr + 8];
        float aA1 = sAl[m_base + 16 + qr], aB1 = sAl[m_base + 24 + qr];
#pragma unroll
        for (int o = 0; o < 8; o++) {
            acc[0][o].x *= aA0; acc[0][o].y *= aA0; acc[0][o].z *= aB0; acc[0][o].w *= aB0;
            acc[1][o].x *= aA1; acc[1][o].y *= aA1; acc[1][o].z *= aB1; acc[1][o].w *= aB1;
        }
#pragma unroll
        for (int ks = 0; ks < 4; ks++) {
            unsigned pa[2][4];
#pragma unroll
            for (int msT = 0; msT < 2; msT++)
                ldm4(pa[msT][0], pa[msT][1], pa[msT][2], pa[msT][3],
                     sbase + (OP + (m_base + 16 * msT + arow) * 36 + ks * 8 + acol) * 4);
#pragma unroll
            for (int otp = 0; otp < 4; otp++) {
                unsigned v0a, v1a, v0b, v1b;
                ldm4(v0a, v1a, v0b, v1b,
                     sbase + (vbw + (o_base + 16 * otp + brow) * 36 + ks * 8 + bcol) * 4);
                mma16(acc[0][2 * otp],     pa[0], v0a, v1a);
                mma16(acc[1][2 * otp],     pa[1], v0a, v1a);
                mma16(acc[0][2 * otp + 1], pa[0], v0b, v1b);
                mma16(acc[1][2 * otp + 1], pa[1], v0b, v1b);
            }
        }

        asm volatile("cp.async.wait_group 0;" ::: "memory");
        __syncthreads();   // next tile ready; P/V consumed
    }

    if (w < 4 && quad == 0) {
        float gm = gamma[0];
        sSc[16 * w + qr]     = gm / run_l0;
        sSc[16 * w + qr + 8] = gm / run_l1;
    }
    __syncthreads();

    const float* xb = x   + (size_t)b * CC * NTOK;
    float*       ob = out + (size_t)b * CC * NTOK;
#pragma unroll
    for (int s = 0; s < 2; s++) {
        int rA = m_base + 16 * s + qr;
        float scA = sSc[rA];
        float scB = sSc[rA + 8];
        int m = q0 + rA;
#pragma unroll
        for (int ot = 0; ot < 8; ot++) {
            int o = o_base + ot * 8 + 2 * quad;
            float4 c = acc[s][ot];
            size_t i00 = (size_t)o * NTOK + m;
            size_t i10 = (size_t)(o + 1) * NTOK + m;
            ob[i00]     = fmaf(scA, c.x, xb[i00]);
            ob[i10]     = fmaf(scA, c.y, xb[i10]);
            ob[i00 + 8] = fmaf(scB, c.z, xb[i00 + 8]);
            ob[i10 + 8] = fmaf(scB, c.w, xb[i10 + 8]);
        }
    }
}

// ============ launch ============
extern "C" void kernel_launch(void* const* d_in, const int* in_sizes, int n_in,
                              void* d_out, int out_size)
{
    const float* x     = (const float*)d_in[0];
    const float* wq    = (const float*)d_in[1];
    const float* bq    = (const float*)d_in[2];
    const float* wk    = (const float*)d_in[3];
    const float* bk    = (const float*)d_in[4];
    const float* wv    = (const float*)d_in[5];
    const float* bv    = (const float*)d_in[6];
    const float* gamma = (const float*)d_in[7];
    float* out = (float*)d_out;

    convw_kernel<<<320, 256>>>(wq, bq, wk, bk, wv, bv);
    convx_kernel<<<dim3(NTOK / 64, CC / 64, BATCH), 256>>>(x);

    const int proj_bytes = PROJ_WORDS * 4;
    cudaFuncSetAttribute(projmma_kernel, cudaFuncAttributeMaxDynamicSharedMemorySize, proj_bytes);
    projmma_kernel<<<dim3(NTOK / 64, 5, BATCH), 256, proj_bytes>>>();

    const int smem_bytes = SMEM_WORDS * 4;   // 94720
    cudaFuncSetAttribute(attn_kernel, cudaFuncAttributeMaxDynamicSharedMemorySize, smem_bytes);
    attn_kernel<<<BATCH * (NTOK / 64), 256, smem_bytes>>>(x, gamma, out);
}